// round 10
// baseline (speedup 1.0000x reference)
#include <cuda_runtime.h>
#include <cuda_fp16.h>
#include <cstdint>

// ---------------------------------------------------------------------------
// Persistent 2-layer LSTM via mma.sync m16n8k16 fp16 (single-plane weights,
// h fp16). 128 CTAs x 256 threads. CTA tile: 16 elems (64 gate-rows) x 64
// batch. Weight slices resident in SMEM (fp16, 96KB). K=256 B-staging stages
// (3 per iteration, 2x32KB double buffer). Flag-based per-group (16 CTA)
// barrier. Merged dual epilogue (one sync). h fp16 [parity][batch][elem].
//
// R9 bugfix: b1 ldmatrix row (+16) must fold +16 into the 32-slot swizzle.
// ---------------------------------------------------------------------------

#define Hs   256
#define Bs   512
#define Ts   512
#define HB   (Hs*Bs)
#define NT   256
#define NCTA 128

// smem byte offsets
#define SM_W(w)   ((w)*32768)           // weight w: 64 rows x 512B = 32KB
#define SM_B      98304                 // B staging: 2 bufs x 32768B
#define SM_DSM1   163840                // [64][68] f32 = 17408B
#define SM_DSM2   181248
#define SM_BIAS1  198656
#define SM_BIAS2  198912
#define SM_W0     199168
#define SMEM_BYTES 199424

// ---- persistent device scratch --------------------------------------------
__device__ __half  g_h1[2*HB];          // [parity][batch][elem] fp16
__device__ __half  g_h2[2*HB];
__device__ float   g_xT[Ts*Bs];
__device__ unsigned g_flag[8*16];       // per-group x per-CTA monotonic flags

// ---- helpers ---------------------------------------------------------------
__device__ __forceinline__ uint32_t smem_u32(const void* p) {
    uint32_t a;
    asm("{ .reg .u64 t; cvta.to.shared.u64 t, %1; cvt.u32.u64 %0, t; }"
        : "=r"(a) : "l"(p));
    return a;
}
__device__ __forceinline__ float tanh_ap(float x) {
    float y; asm("tanh.approx.f32 %0, %1;" : "=f"(y) : "f"(x)); return y;
}
__device__ __forceinline__ float sig_ap(float x) {
    return fmaf(tanh_ap(0.5f * x), 0.5f, 0.5f);
}
__device__ __forceinline__ void ldsm4(unsigned r[4], uint32_t addr) {
    asm volatile("ldmatrix.sync.aligned.m8n8.x4.shared.b16 {%0,%1,%2,%3}, [%4];"
        : "=r"(r[0]), "=r"(r[1]), "=r"(r[2]), "=r"(r[3]) : "r"(addr));
}
__device__ __forceinline__ void sts128(uint32_t addr, uint4 v) {
    asm volatile("st.shared.v4.b32 [%0], {%1,%2,%3,%4};"
        :: "r"(addr), "r"(v.x), "r"(v.y), "r"(v.z), "r"(v.w) : "memory");
}
__device__ __forceinline__ void mma_fp16(float d[4], const unsigned a[4],
                                         unsigned b0, unsigned b1) {
    asm volatile(
        "mma.sync.aligned.m16n8k16.row.col.f32.f16.f16.f32 "
        "{%0,%1,%2,%3}, {%4,%5,%6,%7}, {%8,%9}, {%0,%1,%2,%3};"
        : "+f"(d[0]), "+f"(d[1]), "+f"(d[2]), "+f"(d[3])
        : "r"(a[0]), "r"(a[1]), "r"(a[2]), "r"(a[3]), "r"(b0), "r"(b1));
}
__device__ __forceinline__ unsigned packh2(float a, float b) {
    return (unsigned)__half_as_ushort(__float2half_rn(a))
         | ((unsigned)__half_as_ushort(__float2half_rn(b)) << 16);
}

// ---- flag-based per-group (16 CTA) barrier ----------------------------------
__device__ __forceinline__ void group_barrier(int grp, int mt, unsigned target) {
    __syncthreads();
    if (threadIdx.x == 0) {
        asm volatile("membar.gl;" ::: "memory");
        asm volatile("st.release.gpu.global.u32 [%0], %1;"
                     :: "l"(&g_flag[grp * 16 + mt]), "r"(target) : "memory");
    }
    if (threadIdx.x < 16) {
        unsigned v;
        const unsigned* f = &g_flag[grp * 16 + threadIdx.x];
        do {
            asm volatile("ld.acquire.gpu.global.u32 %0, [%1];"
                         : "=r"(v) : "l"(f));
        } while (v < target);
    }
    __syncthreads();
}

// ---- B staging: full K=256 tile = 64 rows x 512B = 32KB ---------------------
__device__ __forceinline__ void ldgB(uint4 pf[8], const __half* __restrict__ h,
                                     int b0) {
    int n = threadIdx.x >> 2;
    int c0 = (threadIdx.x & 3) * 8;
    const uint4* p = (const uint4*)(h + (size_t)(b0 + n) * Hs) + c0;
    #pragma unroll
    for (int j = 0; j < 8; ++j) pf[j] = __ldcg(p + j);
}
__device__ __forceinline__ void stsB(uint32_t buf, const uint4 pf[8]) {
    int n = threadIdx.x >> 2;
    int c0 = (threadIdx.x & 3) * 8;
    #pragma unroll
    for (int j = 0; j < 8; ++j)
        sts128(buf + n * 512 + (((c0 + j + n) & 31) << 4), pf[j]);
}

// ---- full K=256 GEMM on a staged tile ----------------------------------------
__device__ __forceinline__ void gemm_full(
    uint32_t wBase, uint32_t bBuf, float acc[4][4],
    int m_a, uint32_t aRowOff, int kh_a, int n_b, uint32_t bRowOff, int kh_b)
{
    #pragma unroll
    for (int ks = 0; ks < 16; ++ks) {
        unsigned ah[4], b0[4], b1[4];
        int ca = ks * 2 + kh_a;
        ldsm4(ah, wBase + aRowOff + (((ca + m_a) & 31) << 4));
        int cb = ks * 2 + kh_b;
        // row r swizzles chunk c to slot (c + r) & 31. b0 rows = wn*32 + n_b
        // (wn*32 = 0 mod 32); b1 rows are +16, so fold +16 into the swizzle.
        ldsm4(b0, bBuf + bRowOff + (((cb + n_b) & 31) << 4));
        ldsm4(b1, bBuf + bRowOff + 8192 + (((cb + n_b + 16) & 31) << 4));
        mma_fp16(acc[0], ah, b0[0], b0[1]);
        mma_fp16(acc[1], ah, b0[2], b0[3]);
        mma_fp16(acc[2], ah, b1[0], b1[1]);
        mma_fp16(acc[3], ah, b1[2], b1[3]);
    }
}

// ---- epilogue split: store D tile, then pointwise ----------------------------
__device__ __forceinline__ void epi_store(
    float* __restrict__ Dsm, float acc[4][4], int m0, int wn, int l)
{
    const int qrow = l >> 2, qcol = (l & 3) * 2;
    #pragma unroll
    for (int nt = 0; nt < 4; ++nt) {
        int col = wn * 32 + nt * 8 + qcol;
        *(float2*)&Dsm[(m0 + qrow) * 68 + col]     = make_float2(acc[nt][0], acc[nt][1]);
        *(float2*)&Dsm[(m0 + 8 + qrow) * 68 + col] = make_float2(acc[nt][2], acc[nt][3]);
    }
}
__device__ __forceinline__ void epi_math(
    const float* __restrict__ Dsm, const float* __restrict__ bias_sm,
    const float* __restrict__ w0_sm, float xv, float cst[4],
    __half* __restrict__ hdst, int b0, int e0)
{
    const int tid = threadIdx.x;
    const int bl = tid & 63, eq = tid >> 6;
    unsigned pk[2];
    #pragma unroll
    for (int jj = 0; jj < 2; ++jj) {
        float hv2[2];
        #pragma unroll
        for (int j2 = 0; j2 < 2; ++j2) {
            int j = jj * 2 + j2;
            int el = eq * 4 + j;
            float gi = Dsm[(el)      * 68 + bl] + bias_sm[el];
            float gf = Dsm[(16 + el) * 68 + bl] + bias_sm[16 + el];
            float gg = Dsm[(32 + el) * 68 + bl] + bias_sm[32 + el];
            float go = Dsm[(48 + el) * 68 + bl] + bias_sm[48 + el];
            if (w0_sm) {
                gi = fmaf(xv, w0_sm[el], gi);
                gf = fmaf(xv, w0_sm[16 + el], gf);
                gg = fmaf(xv, w0_sm[32 + el], gg);
                go = fmaf(xv, w0_sm[48 + el], go);
            }
            float iv = sig_ap(gi), fv = sig_ap(gf);
            float gv = tanh_ap(gg), ov = sig_ap(go);
            float c = fv * cst[j] + iv * gv;
            cst[j] = c;
            hv2[j2] = ov * tanh_ap(c);
        }
        pk[jj] = packh2(hv2[0], hv2[1]);
    }
    *(uint2*)&hdst[(size_t)(b0 + bl) * Hs + e0 + eq * 4] = make_uint2(pk[0], pk[1]);
}

// ---------------------------------------------------------------------------
__global__ void __launch_bounds__(NT, 1) lstm_main(
    const float* __restrict__ Wih0, const float* __restrict__ Whh0,
    const float* __restrict__ bih0, const float* __restrict__ bhh0,
    const float* __restrict__ Wih1, const float* __restrict__ Whh1,
    const float* __restrict__ bih1, const float* __restrict__ bhh1)
{
    extern __shared__ char smc[];
    const uint32_t smb = smem_u32(smc);
    const int tid = threadIdx.x;
    const int mt  = blockIdx.x & 15;
    const int grp = blockIdx.x >> 4;
    const int e0  = mt * 16;
    const int b0  = grp * 64;

    // ---- load weight slices into smem (fp16, swizzled) ----
    {
        const float* Wg[3] = {Whh0, Whh1, Wih1};
        int m = tid >> 2;
        int g = m >> 4, el = m & 15;
        for (int w = 0; w < 3; ++w) {
            const float* row = Wg[w] + (size_t)(g * Hs + e0 + el) * Hs;
            uint32_t whi = smb + SM_W(w);
            #pragma unroll
            for (int c8 = 0; c8 < 8; ++c8) {
                int c = (tid & 3) * 8 + c8;
                float4 v0 = *(const float4*)&row[c * 8];
                float4 v1 = *(const float4*)&row[c * 8 + 4];
                uint4 hi = make_uint4(packh2(v0.x, v0.y), packh2(v0.z, v0.w),
                                      packh2(v1.x, v1.y), packh2(v1.z, v1.w));
                sts128(whi + m * 512 + (((c + m) & 31) << 4), hi);
            }
        }
    }
    if (tid < 64) {
        int g = tid >> 4, el = tid & 15;
        int row = g * Hs + e0 + el;
        ((float*)(smc + SM_BIAS1))[tid] = bih0[row] + bhh0[row];
        ((float*)(smc + SM_BIAS2))[tid] = bih1[row] + bhh1[row];
        ((float*)(smc + SM_W0))[tid]    = Wih0[row];
    }
    __syncthreads();

    // lane constants for ldmatrix addressing
    const int wid = tid >> 5, l = tid & 31;
    const int wm = wid & 3, wn = wid >> 2;
    const int m0 = wm * 16;
    const int m_a = m0 + (l & 7) + (((l >> 3) & 1) << 3);
    const uint32_t aRowOff = m_a * 512;
    const int kh_a = l >> 4;
    const int n_b = (l & 7) + (((l >> 4) & 1) << 3);
    const uint32_t bRowOff = (wn * 32 + n_b) * 512;
    const int kh_b = (l >> 3) & 1;

    float* Dsm1 = (float*)(smc + SM_DSM1);
    float* Dsm2 = (float*)(smc + SM_DSM2);
    const float* bias1 = (const float*)(smc + SM_BIAS1);
    const float* bias2 = (const float*)(smc + SM_BIAS2);
    const float* w0sm  = (const float*)(smc + SM_W0);
    const uint32_t buf0 = smb + SM_B;
    const uint32_t buf1 = smb + SM_B + 32768;

    float c1[4] = {0.f, 0.f, 0.f, 0.f};
    float c2[4] = {0.f, 0.f, 0.f, 0.f};
    float acc1[4][4], acc2[4][4];
    uint4 pf[8];

    for (int i = 0; i <= Ts; ++i) {
        const __half* h1p = g_h1 + (size_t)(i & 1) * HB;        // h1(t=i-1)
        __half*       h1d = g_h1 + (size_t)((i + 1) & 1) * HB;  // h1(t=i)
        const __half* h2p = g_h2 + (size_t)((i + 1) & 1) * HB;  // h2(t=i-2)
        __half*       h2d = g_h2 + (size_t)(i & 1) * HB;        // h2(t=i-1)
        const bool doL1 = (i < Ts), doL2 = (i >= 1);
        float xv = doL1 ? g_xT[(size_t)i * Bs + b0 + (tid & 63)] : 0.f;

        #pragma unroll
        for (int nt = 0; nt < 4; ++nt)
            #pragma unroll
            for (int r = 0; r < 4; ++r) { acc1[nt][r] = 0.f; acc2[nt][r] = 0.f; }

        if (doL1) {
            // stage 0: Whh0 x h1p -> acc1
            ldgB(pf, h1p, b0);
            stsB(buf0, pf);
            __syncthreads();
            if (doL2) ldgB(pf, h2p, b0);                    // prefetch stage 1
            gemm_full(smb + SM_W(0), buf0, acc1,
                      m_a, aRowOff, kh_a, n_b, bRowOff, kh_b);
        } else {
            ldgB(pf, h2p, b0);                              // i==Ts entry
        }

        if (doL2) {
            // stage 1: Whh1 x h2p -> acc2
            stsB(buf1, pf);
            __syncthreads();
            ldgB(pf, h1p, b0);                              // prefetch stage 2
            gemm_full(smb + SM_W(1), buf1, acc2,
                      m_a, aRowOff, kh_a, n_b, bRowOff, kh_b);
            // stage 2: Wih1 x h1p -> acc2
            stsB(buf0, pf);
            __syncthreads();
            gemm_full(smb + SM_W(2), buf0, acc2,
                      m_a, aRowOff, kh_a, n_b, bRowOff, kh_b);
        }

        // merged epilogue: one sync for both layers
        if (doL1) epi_store(Dsm1, acc1, m0, wn, l);
        if (doL2) epi_store(Dsm2, acc2, m0, wn, l);
        __syncthreads();
        if (doL1) epi_math(Dsm1, bias1, w0sm, xv, c1, h1d, b0, e0);
        if (doL2) epi_math(Dsm2, bias2, (const float*)0, 0.f, c2, h2d, b0, e0);

        group_barrier(grp, mt, (unsigned)(i + 1));
    }
}

// ---------------------------------------------------------------------------
__global__ void init_states(const float* __restrict__ x) {
    int i0 = blockIdx.x * blockDim.x + threadIdx.x;
    int stride = gridDim.x * blockDim.x;
    unsigned* z1 = (unsigned*)g_h1;
    unsigned* z2 = (unsigned*)g_h2;
    for (int i = i0; i < HB; i += stride) { z1[i] = 0u; z2[i] = 0u; }
    for (int i = i0; i < 8 * 16; i += stride) g_flag[i] = 0u;
    for (int i = i0; i < Ts * Bs; i += stride) {
        int t = i / Bs, b = i % Bs;
        g_xT[i] = x[(size_t)b * Ts + t];
    }
}

// profiling-alignment no-ops (shift ncu's skip window onto lstm_main)
__global__ void dummy_a() {}
__global__ void dummy_b() {}

__global__ void fc_kernel(const float* __restrict__ Wfc,
                          const float* __restrict__ bfc,
                          float* __restrict__ out)
{
    int b = blockIdx.x * blockDim.x + threadIdx.x;   // 0..511
    const __half* h = g_h2;   // final h2(t=511) in parity-0 buffer
    float acc = 0.f;
    #pragma unroll 8
    for (int e = 0; e < Hs; ++e)
        acc += __half2float(h[(size_t)b * Hs + e]) * Wfc[e];
    out[b] = acc + bfc[0];
}

// ---------------------------------------------------------------------------
extern "C" void kernel_launch(void* const* d_in, const int* in_sizes, int n_in,
                              void* d_out, int out_size)
{
    const float* x    = (const float*)d_in[0];
    const float* Wih0 = (const float*)d_in[1];
    const float* Whh0 = (const float*)d_in[2];
    const float* bih0 = (const float*)d_in[3];
    const float* bhh0 = (const float*)d_in[4];
    const float* Wih1 = (const float*)d_in[5];
    const float* Whh1 = (const float*)d_in[6];
    const float* bih1 = (const float*)d_in[7];
    const float* bhh1 = (const float*)d_in[8];
    const float* Wfc  = (const float*)d_in[9];
    const float* bfc  = (const float*)d_in[10];
    float* out = (float*)d_out;

    static bool attr_set = false;
    if (!attr_set) {
        cudaFuncSetAttribute(lstm_main,
            cudaFuncAttributeMaxDynamicSharedMemorySize, SMEM_BYTES);
        attr_set = true;
    }

    init_states<<<512, 256>>>(x);
    dummy_a<<<1, 32>>>();
    dummy_b<<<1, 32>>>();
    lstm_main<<<NCTA, NT, SMEM_BYTES>>>(Wih0, Whh0, bih0, bhh0,
                                        Wih1, Whh1, bih1, bhh1);
    fc_kernel<<<Bs / 256, 256>>>(Wfc, bfc, out);
}

// round 11
// speedup vs baseline: 1.1663x; 1.1663x over previous
#include <cuda_runtime.h>
#include <cuda_fp16.h>
#include <cstdint>

// ---------------------------------------------------------------------------
// Persistent 2-layer LSTM via mma.sync m16n8k16 fp16 (single-plane weights,
// h fp16). 128 CTAs x 256 threads. CTA tile: 16 elems (64 gate-rows) x 64
// batch. Weight slices resident in SMEM (fp16, 96KB). KC=128 B-staging
// chunks (6 per iteration), double-buffered. Flag-based per-group (16 CTA)
// inter-step barrier. h stored fp16 [parity][batch][elem] in global.
//
// R10 lesson: keep ONE live accumulator set + pf[4] (regs ~130, no spills).
// The merged-epilogue / K=256-stage variant hit the 255-reg cap and spilled.
// ---------------------------------------------------------------------------

#define Hs   256
#define Bs   512
#define Ts   512
#define HB   (Hs*Bs)
#define NT   256
#define NCTA 128

// smem byte offsets
#define SM_W(w)   ((w)*32768)           // weight w: 64 rows x 512B = 32KB
#define SM_B      98304                 // B staging: 2 bufs x 16384B
#define SM_DSM    131072                // transpose buf [64][68] f32 = 17408B
#define SM_BIAS1  148480
#define SM_BIAS2  148736
#define SM_W0     148992
#define SMEM_BYTES 149248

// ---- persistent device scratch --------------------------------------------
__device__ __half  g_h1[2*HB];          // [parity][batch][elem] fp16
__device__ __half  g_h2[2*HB];
__device__ float   g_xT[Ts*Bs];
__device__ unsigned g_flag[8*16];       // per-group x per-CTA monotonic flags

// ---- helpers ---------------------------------------------------------------
__device__ __forceinline__ uint32_t smem_u32(const void* p) {
    uint32_t a;
    asm("{ .reg .u64 t; cvta.to.shared.u64 t, %1; cvt.u32.u64 %0, t; }"
        : "=r"(a) : "l"(p));
    return a;
}
__device__ __forceinline__ float tanh_ap(float x) {
    float y; asm("tanh.approx.f32 %0, %1;" : "=f"(y) : "f"(x)); return y;
}
__device__ __forceinline__ float sig_ap(float x) {
    return fmaf(tanh_ap(0.5f * x), 0.5f, 0.5f);
}
__device__ __forceinline__ void ldsm4(unsigned r[4], uint32_t addr) {
    asm volatile("ldmatrix.sync.aligned.m8n8.x4.shared.b16 {%0,%1,%2,%3}, [%4];"
        : "=r"(r[0]), "=r"(r[1]), "=r"(r[2]), "=r"(r[3]) : "r"(addr));
}
__device__ __forceinline__ void sts128(uint32_t addr, uint4 v) {
    asm volatile("st.shared.v4.b32 [%0], {%1,%2,%3,%4};"
        :: "r"(addr), "r"(v.x), "r"(v.y), "r"(v.z), "r"(v.w) : "memory");
}
__device__ __forceinline__ void mma_fp16(float d[4], const unsigned a[4],
                                         unsigned b0, unsigned b1) {
    asm volatile(
        "mma.sync.aligned.m16n8k16.row.col.f32.f16.f16.f32 "
        "{%0,%1,%2,%3}, {%4,%5,%6,%7}, {%8,%9}, {%0,%1,%2,%3};"
        : "+f"(d[0]), "+f"(d[1]), "+f"(d[2]), "+f"(d[3])
        : "r"(a[0]), "r"(a[1]), "r"(a[2]), "r"(a[3]), "r"(b0), "r"(b1));
}
__device__ __forceinline__ unsigned packh2(float a, float b) {
    return (unsigned)__half_as_ushort(__float2half_rn(a))
         | ((unsigned)__half_as_ushort(__float2half_rn(b)) << 16);
}

// ---- flag-based per-group (16 CTA) barrier ----------------------------------
// Arrival: one release store of a monotonic iteration count. Wait: threads
// 0..15 each poll one flag. No atomics, no reset, no sense reversal.
__device__ __forceinline__ void group_barrier(int grp, int mt, unsigned target) {
    __syncthreads();
    if (threadIdx.x == 0) {
        asm volatile("membar.gl;" ::: "memory");
        asm volatile("st.release.gpu.global.u32 [%0], %1;"
                     :: "l"(&g_flag[grp * 16 + mt]), "r"(target) : "memory");
    }
    if (threadIdx.x < 16) {
        unsigned v;
        const unsigned* f = &g_flag[grp * 16 + threadIdx.x];
        do {
            asm volatile("ld.acquire.gpu.global.u32 %0, [%1];"
                         : "=r"(v) : "l"(f));
        } while (v < target);
    }
    __syncthreads();
}

// ---- B staging: chunk = n64 x k128 fp16 = 16KB ------------------------------
__device__ __forceinline__ void ldgB(uint4 pf[4], const __half* __restrict__ h,
                                     int b0, int kc) {
    int n = threadIdx.x >> 2;
    int c0 = (threadIdx.x & 3) * 4;
    const uint4* p = (const uint4*)(h + (size_t)(b0 + n) * Hs + kc * 128 + c0 * 8);
    pf[0] = __ldcg(p);     pf[1] = __ldcg(p + 1);
    pf[2] = __ldcg(p + 2); pf[3] = __ldcg(p + 3);
}
__device__ __forceinline__ void stsB(uint32_t buf, const uint4 pf[4]) {
    int n = threadIdx.x >> 2;
    int c0 = (threadIdx.x & 3) * 4;
    #pragma unroll
    for (int j = 0; j < 4; ++j)
        sts128(buf + n * 256 + (((c0 + j + n) & 15) << 4), pf[j]);
}

// ---- MMA on one staged chunk (KC=128, 8 ksteps) ------------------------------
__device__ __forceinline__ void gemm_chunk(
    uint32_t wBase, uint32_t bBuf, int kcA, float acc[4][4],
    int m_a, uint32_t aRowOff, int kh_a, int n_b, uint32_t bRowOff, int kh_b)
{
    #pragma unroll
    for (int ks = 0; ks < 8; ++ks) {
        unsigned ah[4], b0[4], b1[4];
        int ca = kcA * 16 + ks * 2 + kh_a;
        ldsm4(ah, wBase + aRowOff + (((ca + m_a) & 31) << 4));
        int cb = ks * 2 + kh_b;
        uint32_t bAddr = bBuf + bRowOff + (((cb + n_b) & 15) << 4);
        ldsm4(b0, bAddr);
        ldsm4(b1, bAddr + 4096);          // n +16 rows (+16 ≡ 0 mod 16 swizzle)
        mma_fp16(acc[0], ah, b0[0], b0[1]);
        mma_fp16(acc[1], ah, b0[2], b0[3]);
        mma_fp16(acc[2], ah, b1[0], b1[1]);
        mma_fp16(acc[3], ah, b1[2], b1[3]);
    }
}

// ---- epilogue: one internal sync (Dsm is a dedicated region) -----------------
__device__ __forceinline__ void epilogue(
    float* __restrict__ Dsm, float acc[4][4], int m0, int wn,
    const float* __restrict__ bias_sm, const float* __restrict__ w0_sm,
    float xv, float cst[4], __half* __restrict__ hdst, int b0, int e0)
{
    const int tid = threadIdx.x, l = tid & 31;
    const int qrow = l >> 2, qcol = (l & 3) * 2;
    #pragma unroll
    for (int nt = 0; nt < 4; ++nt) {
        int col = wn * 32 + nt * 8 + qcol;
        *(float2*)&Dsm[(m0 + qrow) * 68 + col]     = make_float2(acc[nt][0], acc[nt][1]);
        *(float2*)&Dsm[(m0 + 8 + qrow) * 68 + col] = make_float2(acc[nt][2], acc[nt][3]);
    }
    __syncthreads();
    const int bl = tid & 63, eq = tid >> 6;
    unsigned pk[2];
    #pragma unroll
    for (int jj = 0; jj < 2; ++jj) {
        float hv2[2];
        #pragma unroll
        for (int j2 = 0; j2 < 2; ++j2) {
            int j = jj * 2 + j2;
            int el = eq * 4 + j;
            float gi = Dsm[(el)      * 68 + bl] + bias_sm[el];
            float gf = Dsm[(16 + el) * 68 + bl] + bias_sm[16 + el];
            float gg = Dsm[(32 + el) * 68 + bl] + bias_sm[32 + el];
            float go = Dsm[(48 + el) * 68 + bl] + bias_sm[48 + el];
            if (w0_sm) {
                gi = fmaf(xv, w0_sm[el], gi);
                gf = fmaf(xv, w0_sm[16 + el], gf);
                gg = fmaf(xv, w0_sm[32 + el], gg);
                go = fmaf(xv, w0_sm[48 + el], go);
            }
            float iv = sig_ap(gi), fv = sig_ap(gf);
            float gv = tanh_ap(gg), ov = sig_ap(go);
            float c = fv * cst[j] + iv * gv;
            cst[j] = c;
            hv2[j2] = ov * tanh_ap(c);
        }
        pk[jj] = packh2(hv2[0], hv2[1]);
    }
    *(uint2*)&hdst[(size_t)(b0 + bl) * Hs + e0 + eq * 4] = make_uint2(pk[0], pk[1]);
}

// ---------------------------------------------------------------------------
__global__ void __launch_bounds__(NT, 1) lstm_main(
    const float* __restrict__ Wih0, const float* __restrict__ Whh0,
    const float* __restrict__ bih0, const float* __restrict__ bhh0,
    const float* __restrict__ Wih1, const float* __restrict__ Whh1,
    const float* __restrict__ bih1, const float* __restrict__ bhh1)
{
    extern __shared__ char smc[];
    const uint32_t smb = smem_u32(smc);
    const int tid = threadIdx.x;
    const int mt  = blockIdx.x & 15;
    const int grp = blockIdx.x >> 4;
    const int e0  = mt * 16;
    const int b0  = grp * 64;

    // ---- load weight slices into smem (fp16 single plane, swizzled) ----
    {
        const float* Wg[3] = {Whh0, Whh1, Wih1};
        int m = tid >> 2;                     // gate-row 0..63
        int g = m >> 4, el = m & 15;
        for (int w = 0; w < 3; ++w) {
            const float* row = Wg[w] + (size_t)(g * Hs + e0 + el) * Hs;
            uint32_t whi = smb + SM_W(w);
            #pragma unroll
            for (int c8 = 0; c8 < 8; ++c8) {
                int c = (tid & 3) * 8 + c8;   // 16B-chunk 0..31
                float4 v0 = *(const float4*)&row[c * 8];
                float4 v1 = *(const float4*)&row[c * 8 + 4];
                uint4 hi = make_uint4(packh2(v0.x, v0.y), packh2(v0.z, v0.w),
                                      packh2(v1.x, v1.y), packh2(v1.z, v1.w));
                sts128(whi + m * 512 + (((c + m) & 31) << 4), hi);
            }
        }
    }
    if (tid < 64) {
        int g = tid >> 4, el = tid & 15;
        int row = g * Hs + e0 + el;
        ((float*)(smc + SM_BIAS1))[tid] = bih0[row] + bhh0[row];
        ((float*)(smc + SM_BIAS2))[tid] = bih1[row] + bhh1[row];
        ((float*)(smc + SM_W0))[tid]    = Wih0[row];
    }
    __syncthreads();

    // lane constants for ldmatrix addressing
    const int wid = tid >> 5, l = tid & 31;
    const int wm = wid & 3, wn = wid >> 2;
    const int m0 = wm * 16;
    const int m_a = m0 + (l & 7) + (((l >> 3) & 1) << 3);
    const uint32_t aRowOff = m_a * 512;
    const int kh_a = l >> 4;
    const int n_b = (l & 7) + (((l >> 4) & 1) << 3);
    const uint32_t bRowOff = (wn * 32 + n_b) * 256;
    const int kh_b = (l >> 3) & 1;

    float* Dsm = (float*)(smc + SM_DSM);
    const float* bias1 = (const float*)(smc + SM_BIAS1);
    const float* bias2 = (const float*)(smc + SM_BIAS2);
    const float* w0sm  = (const float*)(smc + SM_W0);

    float c1[4] = {0.f, 0.f, 0.f, 0.f};
    float c2[4] = {0.f, 0.f, 0.f, 0.f};
    float acc[4][4];
    uint4 pf[4];

    for (int i = 0; i <= Ts; ++i) {
        const __half* h1p = g_h1 + (size_t)(i & 1) * HB;        // h1(t=i-1)
        __half*       h1d = g_h1 + (size_t)((i + 1) & 1) * HB;  // h1(t=i)
        const __half* h2p = g_h2 + (size_t)((i + 1) & 1) * HB;  // h2(t=i-2)
        __half*       h2d = g_h2 + (size_t)(i & 1) * HB;        // h2(t=i-1)

        // chunk schedule (KC=128): ch 0-1 = Whh0 x h1p (L1),
        // ch 2-3 = Whh1 x h2p, ch 4-5 = Wih1 x h1p (L2).
        const int chBeg = (i < Ts) ? 0 : 2;
        const int chEnd = (i >= 1) ? 6 : 2;
        float xv = (i < Ts) ? g_xT[(size_t)i * Bs + b0 + (tid & 63)] : 0.f;

        #pragma unroll
        for (int nt = 0; nt < 4; ++nt)
            #pragma unroll
            for (int r = 0; r < 4; ++r) acc[nt][r] = 0.f;

        ldgB(pf, (chBeg == 2) ? h2p : h1p, b0, chBeg & 1);
        #pragma unroll 1
        for (int ch = chBeg; ch < chEnd; ++ch) {
            uint32_t buf = smb + SM_B + (ch & 1) * 16384;
            stsB(buf, pf);
            __syncthreads();
            if (ch + 1 < chEnd) {
                int nc = ch + 1;
                ldgB(pf, (nc >= 2 && nc < 4) ? h2p : h1p, b0, nc & 1);
            }
            gemm_chunk(smb + SM_W(ch >> 1), buf, ch & 1, acc,
                       m_a, aRowOff, kh_a, n_b, bRowOff, kh_b);
            if (ch == 1) {
                epilogue(Dsm, acc, m0, wn, bias1, w0sm, xv, c1, h1d, b0, e0);
                #pragma unroll
                for (int nt = 0; nt < 4; ++nt)
                    #pragma unroll
                    for (int r = 0; r < 4; ++r) acc[nt][r] = 0.f;
            }
        }
        if (i >= 1)
            epilogue(Dsm, acc, m0, wn, bias2, (const float*)0, 0.f, c2, h2d, b0, e0);

        group_barrier(grp, mt, (unsigned)(i + 1));
    }
}

// ---------------------------------------------------------------------------
__global__ void init_states(const float* __restrict__ x) {
    int i0 = blockIdx.x * blockDim.x + threadIdx.x;
    int stride = gridDim.x * blockDim.x;
    unsigned* z1 = (unsigned*)g_h1;
    unsigned* z2 = (unsigned*)g_h2;
    for (int i = i0; i < HB; i += stride) { z1[i] = 0u; z2[i] = 0u; }
    for (int i = i0; i < 8 * 16; i += stride) g_flag[i] = 0u;
    for (int i = i0; i < Ts * Bs; i += stride) {
        int t = i / Bs, b = i % Bs;
        g_xT[i] = x[(size_t)b * Ts + t];
    }
}

// profiling-alignment no-ops (shift ncu's skip window onto lstm_main)
__global__ void dummy_a() {}
__global__ void dummy_b() {}

__global__ void fc_kernel(const float* __restrict__ Wfc,
                          const float* __restrict__ bfc,
                          float* __restrict__ out)
{
    int b = blockIdx.x * blockDim.x + threadIdx.x;   // 0..511
    const __half* h = g_h2;   // final h2(t=511) in parity-0 buffer
    float acc = 0.f;
    #pragma unroll 8
    for (int e = 0; e < Hs; ++e)
        acc += __half2float(h[(size_t)b * Hs + e]) * Wfc[e];
    out[b] = acc + bfc[0];
}

// ---------------------------------------------------------------------------
extern "C" void kernel_launch(void* const* d_in, const int* in_sizes, int n_in,
                              void* d_out, int out_size)
{
    const float* x    = (const float*)d_in[0];
    const float* Wih0 = (const float*)d_in[1];
    const float* Whh0 = (const float*)d_in[2];
    const float* bih0 = (const float*)d_in[3];
    const float* bhh0 = (const float*)d_in[4];
    const float* Wih1 = (const float*)d_in[5];
    const float* Whh1 = (const float*)d_in[6];
    const float* bih1 = (const float*)d_in[7];
    const float* bhh1 = (const float*)d_in[8];
    const float* Wfc  = (const float*)d_in[9];
    const float* bfc  = (const float*)d_in[10];
    float* out = (float*)d_out;

    static bool attr_set = false;
    if (!attr_set) {
        cudaFuncSetAttribute(lstm_main,
            cudaFuncAttributeMaxDynamicSharedMemorySize, SMEM_BYTES);
        attr_set = true;
    }

    init_states<<<512, 256>>>(x);
    dummy_a<<<1, 32>>>();
    dummy_b<<<1, 32>>>();
    lstm_main<<<NCTA, NT, SMEM_BYTES>>>(Wih0, Whh0, bih0, bhh0,
                                        Wih1, Whh1, bih1, bhh1);
    fc_kernel<<<Bs / 256, 256>>>(Wfc, bfc, out);
}

// round 12
// speedup vs baseline: 1.7946x; 1.5387x over previous
#include <cuda_runtime.h>
#include <cuda_fp16.h>
#include <cstdint>

// ---------------------------------------------------------------------------
// Persistent 2-layer LSTM via mma.sync m16n8k16 fp16 (single-plane weights,
// h fp16). 128 CTAs x 512 threads (16 warps = 4/SMSP for latency hiding).
// CTA tile: 16 elems (64 gate-rows) x 64 batch; warp tile m16 x n16.
// Weight slices resident in SMEM (fp16, 96KB). KC=128 B-staging chunks
// (6 per iteration), double-buffered. R8 atomic+nanosleep per-group barrier
// (R11 lesson: wide no-backoff flag spinning DoSes L2).
// ---------------------------------------------------------------------------

#define Hs   256
#define Bs   512
#define Ts   512
#define HB   (Hs*Bs)
#define NT   512
#define NCTA 128

// smem byte offsets
#define SM_W(w)   ((w)*32768)           // weight w: 64 rows x 512B = 32KB
#define SM_B      98304                 // B staging: 2 bufs x 16384B
#define SM_DSM    131072                // transpose buf [64][68] f32 = 17408B
#define SM_BIAS1  148480
#define SM_BIAS2  148736
#define SM_W0     148992
#define SMEM_BYTES 149248

// ---- persistent device scratch --------------------------------------------
__device__ __half  g_h1[2*HB];          // [parity][batch][elem] fp16
__device__ __half  g_h2[2*HB];
__device__ float   g_xT[Ts*Bs];
__device__ unsigned g_garr[8*128];      // per-group arrive counters (512B apart)
__device__ unsigned g_ggen[8*128];      // per-group generation counters

// ---- helpers ---------------------------------------------------------------
__device__ __forceinline__ uint32_t smem_u32(const void* p) {
    uint32_t a;
    asm("{ .reg .u64 t; cvta.to.shared.u64 t, %1; cvt.u32.u64 %0, t; }"
        : "=r"(a) : "l"(p));
    return a;
}
__device__ __forceinline__ float tanh_ap(float x) {
    float y; asm("tanh.approx.f32 %0, %1;" : "=f"(y) : "f"(x)); return y;
}
__device__ __forceinline__ float sig_ap(float x) {
    return fmaf(tanh_ap(0.5f * x), 0.5f, 0.5f);
}
__device__ __forceinline__ void ldsm4(unsigned r[4], uint32_t addr) {
    asm volatile("ldmatrix.sync.aligned.m8n8.x4.shared.b16 {%0,%1,%2,%3}, [%4];"
        : "=r"(r[0]), "=r"(r[1]), "=r"(r[2]), "=r"(r[3]) : "r"(addr));
}
__device__ __forceinline__ void sts128(uint32_t addr, uint4 v) {
    asm volatile("st.shared.v4.b32 [%0], {%1,%2,%3,%4};"
        :: "r"(addr), "r"(v.x), "r"(v.y), "r"(v.z), "r"(v.w) : "memory");
}
__device__ __forceinline__ void mma_fp16(float d[4], const unsigned a[4],
                                         unsigned b0, unsigned b1) {
    asm volatile(
        "mma.sync.aligned.m16n8k16.row.col.f32.f16.f16.f32 "
        "{%0,%1,%2,%3}, {%4,%5,%6,%7}, {%8,%9}, {%0,%1,%2,%3};"
        : "+f"(d[0]), "+f"(d[1]), "+f"(d[2]), "+f"(d[3])
        : "r"(a[0]), "r"(a[1]), "r"(a[2]), "r"(a[3]), "r"(b0), "r"(b1));
}
__device__ __forceinline__ unsigned packh2(float a, float b) {
    return (unsigned)__half_as_ushort(__float2half_rn(a))
         | ((unsigned)__half_as_ushort(__float2half_rn(b)) << 16);
}

// ---- per-group (16 CTA) barrier: R8 version (atomic + nanosleep poll) -------
__device__ __forceinline__ void group_barrier(int grp) {
    __syncthreads();
    if (threadIdx.x == 0) {
        unsigned* arr = &g_garr[grp * 128];
        unsigned* gen = &g_ggen[grp * 128];
        __threadfence();
        unsigned my;
        asm volatile("ld.acquire.gpu.global.u32 %0, [%1];"
                     : "=r"(my) : "l"(gen));
        if (atomicAdd(arr, 1u) == 15u) {
            atomicExch(arr, 0u);
            __threadfence();
            atomicAdd(gen, 1u);
        } else {
            unsigned v;
            do {
                __nanosleep(16);
                asm volatile("ld.acquire.gpu.global.u32 %0, [%1];"
                             : "=r"(v) : "l"(gen));
            } while (v == my);
        }
    }
    __syncthreads();
}

// ---- B staging: chunk = n64 x k128 fp16 = 16KB, 512 threads ------------------
__device__ __forceinline__ void ldgB(uint4 pf[2], const __half* __restrict__ h,
                                     int b0, int kc) {
    int n  = threadIdx.x >> 3;             // 0..63
    int c0 = (threadIdx.x & 7) * 2;        // 0..14
    const uint4* p = (const uint4*)(h + (size_t)(b0 + n) * Hs + kc * 128 + c0 * 8);
    pf[0] = __ldcg(p); pf[1] = __ldcg(p + 1);
}
__device__ __forceinline__ void stsB(uint32_t buf, const uint4 pf[2]) {
    int n  = threadIdx.x >> 3;
    int c0 = (threadIdx.x & 7) * 2;
    sts128(buf + n * 256 + (((c0 + n) & 15) << 4), pf[0]);
    sts128(buf + n * 256 + (((c0 + 1 + n) & 15) << 4), pf[1]);
}

// ---- MMA on one staged chunk (KC=128, 8 ksteps), warp tile m16 x n16 ---------
__device__ __forceinline__ void gemm_chunk(
    uint32_t wBase, uint32_t bBuf, int kcA, float acc[2][4],
    int m_a, uint32_t aRowOff, int kh_a, int n_b, uint32_t bRowOff, int kh_b)
{
    #pragma unroll
    for (int ks = 0; ks < 8; ++ks) {
        unsigned ah[4], b0[4];
        int ca = kcA * 16 + ks * 2 + kh_a;
        ldsm4(ah, wBase + aRowOff + (((ca + m_a) & 31) << 4));
        int cb = ks * 2 + kh_b;
        ldsm4(b0, bBuf + bRowOff + (((cb + n_b) & 15) << 4));
        mma_fp16(acc[0], ah, b0[0], b0[1]);
        mma_fp16(acc[1], ah, b0[2], b0[3]);
    }
}

// ---- epilogue ----------------------------------------------------------------
__device__ __forceinline__ void epilogue(
    float* __restrict__ Dsm, float acc[2][4], int m0, int wn,
    const float* __restrict__ bias_sm, const float* __restrict__ w0_sm,
    float xv, float cst[2], __half* __restrict__ hdst, int b0, int e0)
{
    const int tid = threadIdx.x, l = tid & 31;
    const int qrow = l >> 2, qcol = (l & 3) * 2;
    #pragma unroll
    for (int nt = 0; nt < 2; ++nt) {
        int col = wn * 16 + nt * 8 + qcol;
        *(float2*)&Dsm[(m0 + qrow) * 68 + col]     = make_float2(acc[nt][0], acc[nt][1]);
        *(float2*)&Dsm[(m0 + 8 + qrow) * 68 + col] = make_float2(acc[nt][2], acc[nt][3]);
    }
    __syncthreads();
    const int bl = tid & 63, eq = tid >> 6;      // eq 0..7 -> elems eq*2, eq*2+1
    float hv2[2];
    #pragma unroll
    for (int j2 = 0; j2 < 2; ++j2) {
        int el = eq * 2 + j2;
        float gi = Dsm[(el)      * 68 + bl] + bias_sm[el];
        float gf = Dsm[(16 + el) * 68 + bl] + bias_sm[16 + el];
        float gg = Dsm[(32 + el) * 68 + bl] + bias_sm[32 + el];
        float go = Dsm[(48 + el) * 68 + bl] + bias_sm[48 + el];
        if (w0_sm) {
            gi = fmaf(xv, w0_sm[el], gi);
            gf = fmaf(xv, w0_sm[16 + el], gf);
            gg = fmaf(xv, w0_sm[32 + el], gg);
            go = fmaf(xv, w0_sm[48 + el], go);
        }
        float iv = sig_ap(gi), fv = sig_ap(gf);
        float gv = tanh_ap(gg), ov = sig_ap(go);
        float c = fv * cst[j2] + iv * gv;
        cst[j2] = c;
        hv2[j2] = ov * tanh_ap(c);
    }
    *(unsigned*)&hdst[(size_t)(b0 + bl) * Hs + e0 + eq * 2] = packh2(hv2[0], hv2[1]);
}

// ---------------------------------------------------------------------------
__global__ void __launch_bounds__(NT, 1) lstm_main(
    const float* __restrict__ Wih0, const float* __restrict__ Whh0,
    const float* __restrict__ bih0, const float* __restrict__ bhh0,
    const float* __restrict__ Wih1, const float* __restrict__ Whh1,
    const float* __restrict__ bih1, const float* __restrict__ bhh1)
{
    extern __shared__ char smc[];
    const uint32_t smb = smem_u32(smc);
    const int tid = threadIdx.x;
    const int mt  = blockIdx.x & 15;
    const int grp = blockIdx.x >> 4;
    const int e0  = mt * 16;
    const int b0  = grp * 64;

    // ---- load weight slices into smem (fp16, swizzled), 512 threads ----
    {
        const float* Wg[3] = {Whh0, Whh1, Wih1};
        int m = tid >> 3;                     // gate-row 0..63
        int g = m >> 4, el = m & 15;
        for (int w = 0; w < 3; ++w) {
            const float* row = Wg[w] + (size_t)(g * Hs + e0 + el) * Hs;
            uint32_t whi = smb + SM_W(w);
            #pragma unroll
            for (int c4 = 0; c4 < 4; ++c4) {
                int c = (tid & 7) * 4 + c4;   // 16B-chunk 0..31
                float4 v0 = *(const float4*)&row[c * 8];
                float4 v1 = *(const float4*)&row[c * 8 + 4];
                uint4 hi = make_uint4(packh2(v0.x, v0.y), packh2(v0.z, v0.w),
                                      packh2(v1.x, v1.y), packh2(v1.z, v1.w));
                sts128(whi + m * 512 + (((c + m) & 31) << 4), hi);
            }
        }
    }
    if (tid < 64) {
        int g = tid >> 4, el = tid & 15;
        int row = g * Hs + e0 + el;
        ((float*)(smc + SM_BIAS1))[tid] = bih0[row] + bhh0[row];
        ((float*)(smc + SM_BIAS2))[tid] = bih1[row] + bhh1[row];
        ((float*)(smc + SM_W0))[tid]    = Wih0[row];
    }
    __syncthreads();

    // lane constants for ldmatrix addressing (16 warps: wm 0..3, wn 0..3)
    const int wid = tid >> 5, l = tid & 31;
    const int wm = wid & 3, wn = wid >> 2;
    const int m0 = wm * 16;
    const int m_a = m0 + (l & 7) + (((l >> 3) & 1) << 3);
    const uint32_t aRowOff = m_a * 512;
    const int kh_a = l >> 4;
    const int n_b = (l & 7) + (((l >> 4) & 1) << 3);
    const uint32_t bRowOff = (wn * 16 + n_b) * 256;   // wn*16 ≡ 0 mod 16 swizzle
    const int kh_b = (l >> 3) & 1;

    float* Dsm = (float*)(smc + SM_DSM);
    const float* bias1 = (const float*)(smc + SM_BIAS1);
    const float* bias2 = (const float*)(smc + SM_BIAS2);
    const float* w0sm  = (const float*)(smc + SM_W0);

    float c1[2] = {0.f, 0.f};
    float c2[2] = {0.f, 0.f};
    float acc[2][4];
    uint4 pf[2];

    for (int i = 0; i <= Ts; ++i) {
        const __half* h1p = g_h1 + (size_t)(i & 1) * HB;        // h1(t=i-1)
        __half*       h1d = g_h1 + (size_t)((i + 1) & 1) * HB;  // h1(t=i)
        const __half* h2p = g_h2 + (size_t)((i + 1) & 1) * HB;  // h2(t=i-2)
        __half*       h2d = g_h2 + (size_t)(i & 1) * HB;        // h2(t=i-1)

        // chunk schedule (KC=128): ch 0-1 = Whh0 x h1p (L1),
        // ch 2-3 = Whh1 x h2p, ch 4-5 = Wih1 x h1p (L2).
        const int chBeg = (i < Ts) ? 0 : 2;
        const int chEnd = (i >= 1) ? 6 : 2;
        float xv = (i < Ts) ? g_xT[(size_t)i * Bs + b0 + (tid & 63)] : 0.f;

        #pragma unroll
        for (int nt = 0; nt < 2; ++nt)
            #pragma unroll
            for (int r = 0; r < 4; ++r) acc[nt][r] = 0.f;

        ldgB(pf, (chBeg == 2) ? h2p : h1p, b0, chBeg & 1);
        #pragma unroll 1
        for (int ch = chBeg; ch < chEnd; ++ch) {
            uint32_t buf = smb + SM_B + (ch & 1) * 16384;
            stsB(buf, pf);
            __syncthreads();
            if (ch + 1 < chEnd) {
                int nc = ch + 1;
                ldgB(pf, (nc >= 2 && nc < 4) ? h2p : h1p, b0, nc & 1);
            }
            gemm_chunk(smb + SM_W(ch >> 1), buf, ch & 1, acc,
                       m_a, aRowOff, kh_a, n_b, bRowOff, kh_b);
            if (ch == 1) {
                epilogue(Dsm, acc, m0, wn, bias1, w0sm, xv, c1, h1d, b0, e0);
                #pragma unroll
                for (int nt = 0; nt < 2; ++nt)
                    #pragma unroll
                    for (int r = 0; r < 4; ++r) acc[nt][r] = 0.f;
            }
        }
        if (i >= 1)
            epilogue(Dsm, acc, m0, wn, bias2, (const float*)0, 0.f, c2, h2d, b0, e0);

        group_barrier(grp);
    }
}

// ---------------------------------------------------------------------------
__global__ void init_states(const float* __restrict__ x) {
    int i0 = blockIdx.x * blockDim.x + threadIdx.x;
    int stride = gridDim.x * blockDim.x;
    unsigned* z1 = (unsigned*)g_h1;
    unsigned* z2 = (unsigned*)g_h2;
    for (int i = i0; i < HB; i += stride) { z1[i] = 0u; z2[i] = 0u; }
    for (int i = i0; i < 8 * 128; i += stride) { g_garr[i] = 0u; g_ggen[i] = 0u; }
    for (int i = i0; i < Ts * Bs; i += stride) {
        int t = i / Bs, b = i % Bs;
        g_xT[i] = x[(size_t)b * Ts + t];
    }
}

// profiling-alignment no-ops (keep ncu slot 5 on lstm_main)
__global__ void dummy_a() {}
__global__ void dummy_b() {}

__global__ void fc_kernel(const float* __restrict__ Wfc,
                          const float* __restrict__ bfc,
                          float* __restrict__ out)
{
    int b = blockIdx.x * blockDim.x + threadIdx.x;   // 0..511
    const __half* h = g_h2;   // final h2(t=511) in parity-0 buffer
    float acc = 0.f;
    #pragma unroll 8
    for (int e = 0; e < Hs; ++e)
        acc += __half2float(h[(size_t)b * Hs + e]) * Wfc[e];
    out[b] = acc + bfc[0];
}

// ---------------------------------------------------------------------------
extern "C" void kernel_launch(void* const* d_in, const int* in_sizes, int n_in,
                              void* d_out, int out_size)
{
    const float* x    = (const float*)d_in[0];
    const float* Wih0 = (const float*)d_in[1];
    const float* Whh0 = (const float*)d_in[2];
    const float* bih0 = (const float*)d_in[3];
    const float* bhh0 = (const float*)d_in[4];
    const float* Wih1 = (const float*)d_in[5];
    const float* Whh1 = (const float*)d_in[6];
    const float* bih1 = (const float*)d_in[7];
    const float* bhh1 = (const float*)d_in[8];
    const float* Wfc  = (const float*)d_in[9];
    const float* bfc  = (const float*)d_in[10];
    float* out = (float*)d_out;

    static bool attr_set = false;
    if (!attr_set) {
        cudaFuncSetAttribute(lstm_main,
            cudaFuncAttributeMaxDynamicSharedMemorySize, SMEM_BYTES);
        attr_set = true;
    }

    init_states<<<512, 256>>>(x);
    dummy_a<<<1, 32>>>();
    dummy_b<<<1, 32>>>();
    lstm_main<<<NCTA, NT, SMEM_BYTES>>>(Wih0, Whh0, bih0, bhh0,
                                        Wih1, Whh1, bih1, bhh1);
    fc_kernel<<<Bs / 256, 256>>>(Wfc, bfc, out);
}

// round 13
// speedup vs baseline: 1.7972x; 1.0015x over previous
#include <cuda_runtime.h>
#include <cuda_fp16.h>
#include <cstdint>

// ---------------------------------------------------------------------------
// Persistent 2-layer LSTM via mma.sync m16n8k16 fp16 (single-plane weights,
// h fp16). 128 CTAs x 512 threads (16 warps = 4/SMSP for latency hiding).
// CTA tile: 16 elems (64 gate-rows) x 64 batch; warp tile m16 x n16.
// Weight slices resident in SMEM (fp16, 96KB). KC=128 B-staging chunks
// (6 per iteration), double-buffered. R8 atomic+nanosleep per-group barrier
// (R11 lesson: wide no-backoff flag spinning DoSes L2).
// ---------------------------------------------------------------------------

#define Hs   256
#define Bs   512
#define Ts   512
#define HB   (Hs*Bs)
#define NT   512
#define NCTA 128

// smem byte offsets
#define SM_W(w)   ((w)*32768)           // weight w: 64 rows x 512B = 32KB
#define SM_B      98304                 // B staging: 2 bufs x 16384B
#define SM_DSM    131072                // transpose buf [64][68] f32 = 17408B
#define SM_BIAS1  148480
#define SM_BIAS2  148736
#define SM_W0     148992
#define SMEM_BYTES 149248

// ---- persistent device scratch --------------------------------------------
__device__ __half  g_h1[2*HB];          // [parity][batch][elem] fp16
__device__ __half  g_h2[2*HB];
__device__ float   g_xT[Ts*Bs];
__device__ unsigned g_garr[8*128];      // per-group arrive counters (512B apart)
__device__ unsigned g_ggen[8*128];      // per-group generation counters

// ---- helpers ---------------------------------------------------------------
__device__ __forceinline__ uint32_t smem_u32(const void* p) {
    uint32_t a;
    asm("{ .reg .u64 t; cvta.to.shared.u64 t, %1; cvt.u32.u64 %0, t; }"
        : "=r"(a) : "l"(p));
    return a;
}
__device__ __forceinline__ float tanh_ap(float x) {
    float y; asm("tanh.approx.f32 %0, %1;" : "=f"(y) : "f"(x)); return y;
}
__device__ __forceinline__ float sig_ap(float x) {
    return fmaf(tanh_ap(0.5f * x), 0.5f, 0.5f);
}
__device__ __forceinline__ void ldsm4(unsigned r[4], uint32_t addr) {
    asm volatile("ldmatrix.sync.aligned.m8n8.x4.shared.b16 {%0,%1,%2,%3}, [%4];"
        : "=r"(r[0]), "=r"(r[1]), "=r"(r[2]), "=r"(r[3]) : "r"(addr));
}
__device__ __forceinline__ void sts128(uint32_t addr, uint4 v) {
    asm volatile("st.shared.v4.b32 [%0], {%1,%2,%3,%4};"
        :: "r"(addr), "r"(v.x), "r"(v.y), "r"(v.z), "r"(v.w) : "memory");
}
__device__ __forceinline__ void mma_fp16(float d[4], const unsigned a[4],
                                         unsigned b0, unsigned b1) {
    asm volatile(
        "mma.sync.aligned.m16n8k16.row.col.f32.f16.f16.f32 "
        "{%0,%1,%2,%3}, {%4,%5,%6,%7}, {%8,%9}, {%0,%1,%2,%3};"
        : "+f"(d[0]), "+f"(d[1]), "+f"(d[2]), "+f"(d[3])
        : "r"(a[0]), "r"(a[1]), "r"(a[2]), "r"(a[3]), "r"(b0), "r"(b1));
}
__device__ __forceinline__ unsigned packh2(float a, float b) {
    return (unsigned)__half_as_ushort(__float2half_rn(a))
         | ((unsigned)__half_as_ushort(__float2half_rn(b)) << 16);
}

// ---- per-group (16 CTA) barrier: R8 version (atomic + nanosleep poll) -------
__device__ __forceinline__ void group_barrier(int grp) {
    __syncthreads();
    if (threadIdx.x == 0) {
        unsigned* arr = &g_garr[grp * 128];
        unsigned* gen = &g_ggen[grp * 128];
        __threadfence();
        unsigned my;
        asm volatile("ld.acquire.gpu.global.u32 %0, [%1];"
                     : "=r"(my) : "l"(gen));
        if (atomicAdd(arr, 1u) == 15u) {
            atomicExch(arr, 0u);
            __threadfence();
            atomicAdd(gen, 1u);
        } else {
            unsigned v;
            do {
                __nanosleep(16);
                asm volatile("ld.acquire.gpu.global.u32 %0, [%1];"
                             : "=r"(v) : "l"(gen));
            } while (v == my);
        }
    }
    __syncthreads();
}

// ---- B staging: chunk = n64 x k128 fp16 = 16KB, 512 threads ------------------
__device__ __forceinline__ void ldgB(uint4 pf[2], const __half* __restrict__ h,
                                     int b0, int kc) {
    int n  = threadIdx.x >> 3;             // 0..63
    int c0 = (threadIdx.x & 7) * 2;        // 0..14
    const uint4* p = (const uint4*)(h + (size_t)(b0 + n) * Hs + kc * 128 + c0 * 8);
    pf[0] = __ldcg(p); pf[1] = __ldcg(p + 1);
}
__device__ __forceinline__ void stsB(uint32_t buf, const uint4 pf[2]) {
    int n  = threadIdx.x >> 3;
    int c0 = (threadIdx.x & 7) * 2;
    sts128(buf + n * 256 + (((c0 + n) & 15) << 4), pf[0]);
    sts128(buf + n * 256 + (((c0 + 1 + n) & 15) << 4), pf[1]);
}

// ---- MMA on one staged chunk (KC=128, 8 ksteps), warp tile m16 x n16 ---------
__device__ __forceinline__ void gemm_chunk(
    uint32_t wBase, uint32_t bBuf, int kcA, float acc[2][4],
    int m_a, uint32_t aRowOff, int kh_a, int n_b, uint32_t bRowOff, int kh_b)
{
    #pragma unroll
    for (int ks = 0; ks < 8; ++ks) {
        unsigned ah[4], b0[4];
        int ca = kcA * 16 + ks * 2 + kh_a;
        ldsm4(ah, wBase + aRowOff + (((ca + m_a) & 31) << 4));
        int cb = ks * 2 + kh_b;
        ldsm4(b0, bBuf + bRowOff + (((cb + n_b) & 15) << 4));
        mma_fp16(acc[0], ah, b0[0], b0[1]);
        mma_fp16(acc[1], ah, b0[2], b0[3]);
    }
}

// ---- epilogue ----------------------------------------------------------------
__device__ __forceinline__ void epilogue(
    float* __restrict__ Dsm, float acc[2][4], int m0, int wn,
    const float* __restrict__ bias_sm, const float* __restrict__ w0_sm,
    float xv, float cst[2], __half* __restrict__ hdst, int b0, int e0)
{
    const int tid = threadIdx.x, l = tid & 31;
    const int qrow = l >> 2, qcol = (l & 3) * 2;
    #pragma unroll
    for (int nt = 0; nt < 2; ++nt) {
        int col = wn * 16 + nt * 8 + qcol;
        *(float2*)&Dsm[(m0 + qrow) * 68 + col]     = make_float2(acc[nt][0], acc[nt][1]);
        *(float2*)&Dsm[(m0 + 8 + qrow) * 68 + col] = make_float2(acc[nt][2], acc[nt][3]);
    }
    __syncthreads();
    const int bl = tid & 63, eq = tid >> 6;      // eq 0..7 -> elems eq*2, eq*2+1
    float hv2[2];
    #pragma unroll
    for (int j2 = 0; j2 < 2; ++j2) {
        int el = eq * 2 + j2;
        float gi = Dsm[(el)      * 68 + bl] + bias_sm[el];
        float gf = Dsm[(16 + el) * 68 + bl] + bias_sm[16 + el];
        float gg = Dsm[(32 + el) * 68 + bl] + bias_sm[32 + el];
        float go = Dsm[(48 + el) * 68 + bl] + bias_sm[48 + el];
        if (w0_sm) {
            gi = fmaf(xv, w0_sm[el], gi);
            gf = fmaf(xv, w0_sm[16 + el], gf);
            gg = fmaf(xv, w0_sm[32 + el], gg);
            go = fmaf(xv, w0_sm[48 + el], go);
        }
        float iv = sig_ap(gi), fv = sig_ap(gf);
        float gv = tanh_ap(gg), ov = sig_ap(go);
        float c = fv * cst[j2] + iv * gv;
        cst[j2] = c;
        hv2[j2] = ov * tanh_ap(c);
    }
    *(unsigned*)&hdst[(size_t)(b0 + bl) * Hs + e0 + eq * 2] = packh2(hv2[0], hv2[1]);
}

// ---------------------------------------------------------------------------
__global__ void __launch_bounds__(NT, 1) lstm_main(
    const float* __restrict__ Wih0, const float* __restrict__ Whh0,
    const float* __restrict__ bih0, const float* __restrict__ bhh0,
    const float* __restrict__ Wih1, const float* __restrict__ Whh1,
    const float* __restrict__ bih1, const float* __restrict__ bhh1)
{
    extern __shared__ char smc[];
    const uint32_t smb = smem_u32(smc);
    const int tid = threadIdx.x;
    const int mt  = blockIdx.x & 15;
    const int grp = blockIdx.x >> 4;
    const int e0  = mt * 16;
    const int b0  = grp * 64;

    // ---- load weight slices into smem (fp16, swizzled), 512 threads ----
    {
        const float* Wg[3] = {Whh0, Whh1, Wih1};
        int m = tid >> 3;                     // gate-row 0..63
        int g = m >> 4, el = m & 15;
        for (int w = 0; w < 3; ++w) {
            const float* row = Wg[w] + (size_t)(g * Hs + e0 + el) * Hs;
            uint32_t whi = smb + SM_W(w);
            #pragma unroll
            for (int c4 = 0; c4 < 4; ++c4) {
                int c = (tid & 7) * 4 + c4;   // 16B-chunk 0..31
                float4 v0 = *(const float4*)&row[c * 8];
                float4 v1 = *(const float4*)&row[c * 8 + 4];
                uint4 hi = make_uint4(packh2(v0.x, v0.y), packh2(v0.z, v0.w),
                                      packh2(v1.x, v1.y), packh2(v1.z, v1.w));
                sts128(whi + m * 512 + (((c + m) & 31) << 4), hi);
            }
        }
    }
    if (tid < 64) {
        int g = tid >> 4, el = tid & 15;
        int row = g * Hs + e0 + el;
        ((float*)(smc + SM_BIAS1))[tid] = bih0[row] + bhh0[row];
        ((float*)(smc + SM_BIAS2))[tid] = bih1[row] + bhh1[row];
        ((float*)(smc + SM_W0))[tid]    = Wih0[row];
    }
    __syncthreads();

    // lane constants for ldmatrix addressing (16 warps: wm 0..3, wn 0..3)
    const int wid = tid >> 5, l = tid & 31;
    const int wm = wid & 3, wn = wid >> 2;
    const int m0 = wm * 16;
    const int m_a = m0 + (l & 7) + (((l >> 3) & 1) << 3);
    const uint32_t aRowOff = m_a * 512;
    const int kh_a = l >> 4;
    const int n_b = (l & 7) + (((l >> 4) & 1) << 3);
    const uint32_t bRowOff = (wn * 16 + n_b) * 256;   // wn*16 ≡ 0 mod 16 swizzle
    const int kh_b = (l >> 3) & 1;

    float* Dsm = (float*)(smc + SM_DSM);
    const float* bias1 = (const float*)(smc + SM_BIAS1);
    const float* bias2 = (const float*)(smc + SM_BIAS2);
    const float* w0sm  = (const float*)(smc + SM_W0);

    float c1[2] = {0.f, 0.f};
    float c2[2] = {0.f, 0.f};
    float acc[2][4];
    uint4 pf[2];

    for (int i = 0; i <= Ts; ++i) {
        const __half* h1p = g_h1 + (size_t)(i & 1) * HB;        // h1(t=i-1)
        __half*       h1d = g_h1 + (size_t)((i + 1) & 1) * HB;  // h1(t=i)
        const __half* h2p = g_h2 + (size_t)((i + 1) & 1) * HB;  // h2(t=i-2)
        __half*       h2d = g_h2 + (size_t)(i & 1) * HB;        // h2(t=i-1)

        // chunk schedule (KC=128): ch 0-1 = Whh0 x h1p (L1),
        // ch 2-3 = Whh1 x h2p, ch 4-5 = Wih1 x h1p (L2).
        const int chBeg = (i < Ts) ? 0 : 2;
        const int chEnd = (i >= 1) ? 6 : 2;
        float xv = (i < Ts) ? g_xT[(size_t)i * Bs + b0 + (tid & 63)] : 0.f;

        #pragma unroll
        for (int nt = 0; nt < 2; ++nt)
            #pragma unroll
            for (int r = 0; r < 4; ++r) acc[nt][r] = 0.f;

        ldgB(pf, (chBeg == 2) ? h2p : h1p, b0, chBeg & 1);
        #pragma unroll 1
        for (int ch = chBeg; ch < chEnd; ++ch) {
            uint32_t buf = smb + SM_B + (ch & 1) * 16384;
            stsB(buf, pf);
            __syncthreads();
            if (ch + 1 < chEnd) {
                int nc = ch + 1;
                ldgB(pf, (nc >= 2 && nc < 4) ? h2p : h1p, b0, nc & 1);
            }
            gemm_chunk(smb + SM_W(ch >> 1), buf, ch & 1, acc,
                       m_a, aRowOff, kh_a, n_b, bRowOff, kh_b);
            if (ch == 1) {
                epilogue(Dsm, acc, m0, wn, bias1, w0sm, xv, c1, h1d, b0, e0);
                #pragma unroll
                for (int nt = 0; nt < 2; ++nt)
                    #pragma unroll
                    for (int r = 0; r < 4; ++r) acc[nt][r] = 0.f;
            }
        }
        if (i >= 1)
            epilogue(Dsm, acc, m0, wn, bias2, (const float*)0, 0.f, c2, h2d, b0, e0);

        group_barrier(grp);
    }
}

// ---------------------------------------------------------------------------
__global__ void init_states(const float* __restrict__ x) {
    int i0 = blockIdx.x * blockDim.x + threadIdx.x;
    int stride = gridDim.x * blockDim.x;
    unsigned* z1 = (unsigned*)g_h1;
    unsigned* z2 = (unsigned*)g_h2;
    for (int i = i0; i < HB; i += stride) { z1[i] = 0u; z2[i] = 0u; }
    for (int i = i0; i < 8 * 128; i += stride) { g_garr[i] = 0u; g_ggen[i] = 0u; }
    for (int i = i0; i < Ts * Bs; i += stride) {
        int t = i / Bs, b = i % Bs;
        g_xT[i] = x[(size_t)b * Ts + t];
    }
}

// profiling-alignment no-ops (keep ncu slot 5 on lstm_main)
__global__ void dummy_a() {}
__global__ void dummy_b() {}

__global__ void fc_kernel(const float* __restrict__ Wfc,
                          const float* __restrict__ bfc,
                          float* __restrict__ out)
{
    int b = blockIdx.x * blockDim.x + threadIdx.x;   // 0..511
    const __half* h = g_h2;   // final h2(t=511) in parity-0 buffer
    float acc = 0.f;
    #pragma unroll 8
    for (int e = 0; e < Hs; ++e)
        acc += __half2float(h[(size_t)b * Hs + e]) * Wfc[e];
    out[b] = acc + bfc[0];
}

// ---------------------------------------------------------------------------
extern "C" void kernel_launch(void* const* d_in, const int* in_sizes, int n_in,
                              void* d_out, int out_size)
{
    const float* x    = (const float*)d_in[0];
    const float* Wih0 = (const float*)d_in[1];
    const float* Whh0 = (const float*)d_in[2];
    const float* bih0 = (const float*)d_in[3];
    const float* bhh0 = (const float*)d_in[4];
    const float* Wih1 = (const float*)d_in[5];
    const float* Whh1 = (const float*)d_in[6];
    const float* bih1 = (const float*)d_in[7];
    const float* bhh1 = (const float*)d_in[8];
    const float* Wfc  = (const float*)d_in[9];
    const float* bfc  = (const float*)d_in[10];
    float* out = (float*)d_out;

    static bool attr_set = false;
    if (!attr_set) {
        cudaFuncSetAttribute(lstm_main,
            cudaFuncAttributeMaxDynamicSharedMemorySize, SMEM_BYTES);
        attr_set = true;
    }

    init_states<<<512, 256>>>(x);
    dummy_a<<<1, 32>>>();
    dummy_b<<<1, 32>>>();
    lstm_main<<<NCTA, NT, SMEM_BYTES>>>(Wih0, Whh0, bih0, bhh0,
                                        Wih1, Whh1, bih1, bhh1);
    fc_kernel<<<Bs / 256, 256>>>(Wfc, bfc, out);
}

// round 14
// speedup vs baseline: 1.7981x; 1.0005x over previous
#include <cuda_runtime.h>
#include <cuda_fp16.h>
#include <cstdint>

// ---------------------------------------------------------------------------
// Persistent 2-layer LSTM via mma.sync m16n8k16 fp16 (single-plane weights,
// h fp16). 128 CTAs x 512 threads (16 warps = 4/SMSP for latency hiding).
// CTA tile: 16 elems (64 gate-rows) x 64 batch; warp tile m16 x n16.
// Weight slices resident in SMEM (fp16, 96KB). KC=128 B-staging chunks
// (6 per iteration), double-buffered. R8 atomic+nanosleep per-group barrier
// (R11 lesson: wide no-backoff flag spinning DoSes L2).
// ---------------------------------------------------------------------------

#define Hs   256
#define Bs   512
#define Ts   512
#define HB   (Hs*Bs)
#define NT   512
#define NCTA 128

// smem byte offsets
#define SM_W(w)   ((w)*32768)           // weight w: 64 rows x 512B = 32KB
#define SM_B      98304                 // B staging: 2 bufs x 16384B
#define SM_DSM    131072                // transpose buf [64][68] f32 = 17408B
#define SM_BIAS1  148480
#define SM_BIAS2  148736
#define SM_W0     148992
#define SMEM_BYTES 149248

// ---- persistent device scratch --------------------------------------------
__device__ __half  g_h1[2*HB];          // [parity][batch][elem] fp16
__device__ __half  g_h2[2*HB];
__device__ float   g_xT[Ts*Bs];
__device__ unsigned g_garr[8*128];      // per-group arrive counters (512B apart)
__device__ unsigned g_ggen[8*128];      // per-group generation counters

// ---- helpers ---------------------------------------------------------------
__device__ __forceinline__ uint32_t smem_u32(const void* p) {
    uint32_t a;
    asm("{ .reg .u64 t; cvta.to.shared.u64 t, %1; cvt.u32.u64 %0, t; }"
        : "=r"(a) : "l"(p));
    return a;
}
__device__ __forceinline__ float tanh_ap(float x) {
    float y; asm("tanh.approx.f32 %0, %1;" : "=f"(y) : "f"(x)); return y;
}
__device__ __forceinline__ float sig_ap(float x) {
    return fmaf(tanh_ap(0.5f * x), 0.5f, 0.5f);
}
__device__ __forceinline__ void ldsm4(unsigned r[4], uint32_t addr) {
    asm volatile("ldmatrix.sync.aligned.m8n8.x4.shared.b16 {%0,%1,%2,%3}, [%4];"
        : "=r"(r[0]), "=r"(r[1]), "=r"(r[2]), "=r"(r[3]) : "r"(addr));
}
__device__ __forceinline__ void sts128(uint32_t addr, uint4 v) {
    asm volatile("st.shared.v4.b32 [%0], {%1,%2,%3,%4};"
        :: "r"(addr), "r"(v.x), "r"(v.y), "r"(v.z), "r"(v.w) : "memory");
}
__device__ __forceinline__ void mma_fp16(float d[4], const unsigned a[4],
                                         unsigned b0, unsigned b1) {
    asm volatile(
        "mma.sync.aligned.m16n8k16.row.col.f32.f16.f16.f32 "
        "{%0,%1,%2,%3}, {%4,%5,%6,%7}, {%8,%9}, {%0,%1,%2,%3};"
        : "+f"(d[0]), "+f"(d[1]), "+f"(d[2]), "+f"(d[3])
        : "r"(a[0]), "r"(a[1]), "r"(a[2]), "r"(a[3]), "r"(b0), "r"(b1));
}
__device__ __forceinline__ unsigned packh2(float a, float b) {
    return (unsigned)__half_as_ushort(__float2half_rn(a))
         | ((unsigned)__half_as_ushort(__float2half_rn(b)) << 16);
}

// ---- per-group (16 CTA) barrier: R8 version (atomic + nanosleep poll) -------
__device__ __forceinline__ void group_barrier(int grp) {
    __syncthreads();
    if (threadIdx.x == 0) {
        unsigned* arr = &g_garr[grp * 128];
        unsigned* gen = &g_ggen[grp * 128];
        __threadfence();
        unsigned my;
        asm volatile("ld.acquire.gpu.global.u32 %0, [%1];"
                     : "=r"(my) : "l"(gen));
        if (atomicAdd(arr, 1u) == 15u) {
            atomicExch(arr, 0u);
            __threadfence();
            atomicAdd(gen, 1u);
        } else {
            unsigned v;
            do {
                __nanosleep(16);
                asm volatile("ld.acquire.gpu.global.u32 %0, [%1];"
                             : "=r"(v) : "l"(gen));
            } while (v == my);
        }
    }
    __syncthreads();
}

// ---- B staging: chunk = n64 x k128 fp16 = 16KB, 512 threads ------------------
__device__ __forceinline__ void ldgB(uint4 pf[2], const __half* __restrict__ h,
                                     int b0, int kc) {
    int n  = threadIdx.x >> 3;             // 0..63
    int c0 = (threadIdx.x & 7) * 2;        // 0..14
    const uint4* p = (const uint4*)(h + (size_t)(b0 + n) * Hs + kc * 128 + c0 * 8);
    pf[0] = __ldcg(p); pf[1] = __ldcg(p + 1);
}
__device__ __forceinline__ void stsB(uint32_t buf, const uint4 pf[2]) {
    int n  = threadIdx.x >> 3;
    int c0 = (threadIdx.x & 7) * 2;
    sts128(buf + n * 256 + (((c0 + n) & 15) << 4), pf[0]);
    sts128(buf + n * 256 + (((c0 + 1 + n) & 15) << 4), pf[1]);
}

// ---- MMA on one staged chunk (KC=128, 8 ksteps), warp tile m16 x n16 ---------
__device__ __forceinline__ void gemm_chunk(
    uint32_t wBase, uint32_t bBuf, int kcA, float acc[2][4],
    int m_a, uint32_t aRowOff, int kh_a, int n_b, uint32_t bRowOff, int kh_b)
{
    #pragma unroll
    for (int ks = 0; ks < 8; ++ks) {
        unsigned ah[4], b0[4];
        int ca = kcA * 16 + ks * 2 + kh_a;
        ldsm4(ah, wBase + aRowOff + (((ca + m_a) & 31) << 4));
        int cb = ks * 2 + kh_b;
        ldsm4(b0, bBuf + bRowOff + (((cb + n_b) & 15) << 4));
        mma_fp16(acc[0], ah, b0[0], b0[1]);
        mma_fp16(acc[1], ah, b0[2], b0[3]);
    }
}

// ---- epilogue ----------------------------------------------------------------
__device__ __forceinline__ void epilogue(
    float* __restrict__ Dsm, float acc[2][4], int m0, int wn,
    const float* __restrict__ bias_sm, const float* __restrict__ w0_sm,
    float xv, float cst[2], __half* __restrict__ hdst, int b0, int e0)
{
    const int tid = threadIdx.x, l = tid & 31;
    const int qrow = l >> 2, qcol = (l & 3) * 2;
    #pragma unroll
    for (int nt = 0; nt < 2; ++nt) {
        int col = wn * 16 + nt * 8 + qcol;
        *(float2*)&Dsm[(m0 + qrow) * 68 + col]     = make_float2(acc[nt][0], acc[nt][1]);
        *(float2*)&Dsm[(m0 + 8 + qrow) * 68 + col] = make_float2(acc[nt][2], acc[nt][3]);
    }
    __syncthreads();
    const int bl = tid & 63, eq = tid >> 6;      // eq 0..7 -> elems eq*2, eq*2+1
    float hv2[2];
    #pragma unroll
    for (int j2 = 0; j2 < 2; ++j2) {
        int el = eq * 2 + j2;
        float gi = Dsm[(el)      * 68 + bl] + bias_sm[el];
        float gf = Dsm[(16 + el) * 68 + bl] + bias_sm[16 + el];
        float gg = Dsm[(32 + el) * 68 + bl] + bias_sm[32 + el];
        float go = Dsm[(48 + el) * 68 + bl] + bias_sm[48 + el];
        if (w0_sm) {
            gi = fmaf(xv, w0_sm[el], gi);
            gf = fmaf(xv, w0_sm[16 + el], gf);
            gg = fmaf(xv, w0_sm[32 + el], gg);
            go = fmaf(xv, w0_sm[48 + el], go);
        }
        float iv = sig_ap(gi), fv = sig_ap(gf);
        float gv = tanh_ap(gg), ov = sig_ap(go);
        float c = fv * cst[j2] + iv * gv;
        cst[j2] = c;
        hv2[j2] = ov * tanh_ap(c);
    }
    *(unsigned*)&hdst[(size_t)(b0 + bl) * Hs + e0 + eq * 2] = packh2(hv2[0], hv2[1]);
}

// ---------------------------------------------------------------------------
__global__ void __launch_bounds__(NT, 1) lstm_main(
    const float* __restrict__ Wih0, const float* __restrict__ Whh0,
    const float* __restrict__ bih0, const float* __restrict__ bhh0,
    const float* __restrict__ Wih1, const float* __restrict__ Whh1,
    const float* __restrict__ bih1, const float* __restrict__ bhh1)
{
    extern __shared__ char smc[];
    const uint32_t smb = smem_u32(smc);
    const int tid = threadIdx.x;
    const int mt  = blockIdx.x & 15;
    const int grp = blockIdx.x >> 4;
    const int e0  = mt * 16;
    const int b0  = grp * 64;

    // ---- load weight slices into smem (fp16, swizzled), 512 threads ----
    {
        const float* Wg[3] = {Whh0, Whh1, Wih1};
        int m = tid >> 3;                     // gate-row 0..63
        int g = m >> 4, el = m & 15;
        for (int w = 0; w < 3; ++w) {
            const float* row = Wg[w] + (size_t)(g * Hs + e0 + el) * Hs;
            uint32_t whi = smb + SM_W(w);
            #pragma unroll
            for (int c4 = 0; c4 < 4; ++c4) {
                int c = (tid & 7) * 4 + c4;   // 16B-chunk 0..31
                float4 v0 = *(const float4*)&row[c * 8];
                float4 v1 = *(const float4*)&row[c * 8 + 4];
                uint4 hi = make_uint4(packh2(v0.x, v0.y), packh2(v0.z, v0.w),
                                      packh2(v1.x, v1.y), packh2(v1.z, v1.w));
                sts128(whi + m * 512 + (((c + m) & 31) << 4), hi);
            }
        }
    }
    if (tid < 64) {
        int g = tid >> 4, el = tid & 15;
        int row = g * Hs + e0 + el;
        ((float*)(smc + SM_BIAS1))[tid] = bih0[row] + bhh0[row];
        ((float*)(smc + SM_BIAS2))[tid] = bih1[row] + bhh1[row];
        ((float*)(smc + SM_W0))[tid]    = Wih0[row];
    }
    __syncthreads();

    // lane constants for ldmatrix addressing (16 warps: wm 0..3, wn 0..3)
    const int wid = tid >> 5, l = tid & 31;
    const int wm = wid & 3, wn = wid >> 2;
    const int m0 = wm * 16;
    const int m_a = m0 + (l & 7) + (((l >> 3) & 1) << 3);
    const uint32_t aRowOff = m_a * 512;
    const int kh_a = l >> 4;
    const int n_b = (l & 7) + (((l >> 4) & 1) << 3);
    const uint32_t bRowOff = (wn * 16 + n_b) * 256;   // wn*16 ≡ 0 mod 16 swizzle
    const int kh_b = (l >> 3) & 1;

    float* Dsm = (float*)(smc + SM_DSM);
    const float* bias1 = (const float*)(smc + SM_BIAS1);
    const float* bias2 = (const float*)(smc + SM_BIAS2);
    const float* w0sm  = (const float*)(smc + SM_W0);

    float c1[2] = {0.f, 0.f};
    float c2[2] = {0.f, 0.f};
    float acc[2][4];
    uint4 pf[2];

    for (int i = 0; i <= Ts; ++i) {
        const __half* h1p = g_h1 + (size_t)(i & 1) * HB;        // h1(t=i-1)
        __half*       h1d = g_h1 + (size_t)((i + 1) & 1) * HB;  // h1(t=i)
        const __half* h2p = g_h2 + (size_t)((i + 1) & 1) * HB;  // h2(t=i-2)
        __half*       h2d = g_h2 + (size_t)(i & 1) * HB;        // h2(t=i-1)

        // chunk schedule (KC=128): ch 0-1 = Whh0 x h1p (L1),
        // ch 2-3 = Whh1 x h2p, ch 4-5 = Wih1 x h1p (L2).
        const int chBeg = (i < Ts) ? 0 : 2;
        const int chEnd = (i >= 1) ? 6 : 2;
        float xv = (i < Ts) ? g_xT[(size_t)i * Bs + b0 + (tid & 63)] : 0.f;

        #pragma unroll
        for (int nt = 0; nt < 2; ++nt)
            #pragma unroll
            for (int r = 0; r < 4; ++r) acc[nt][r] = 0.f;

        ldgB(pf, (chBeg == 2) ? h2p : h1p, b0, chBeg & 1);
        #pragma unroll 1
        for (int ch = chBeg; ch < chEnd; ++ch) {
            uint32_t buf = smb + SM_B + (ch & 1) * 16384;
            stsB(buf, pf);
            __syncthreads();
            if (ch + 1 < chEnd) {
                int nc = ch + 1;
                ldgB(pf, (nc >= 2 && nc < 4) ? h2p : h1p, b0, nc & 1);
            }
            gemm_chunk(smb + SM_W(ch >> 1), buf, ch & 1, acc,
                       m_a, aRowOff, kh_a, n_b, bRowOff, kh_b);
            if (ch == 1) {
                epilogue(Dsm, acc, m0, wn, bias1, w0sm, xv, c1, h1d, b0, e0);
                #pragma unroll
                for (int nt = 0; nt < 2; ++nt)
                    #pragma unroll
                    for (int r = 0; r < 4; ++r) acc[nt][r] = 0.f;
            }
        }
        if (i >= 1)
            epilogue(Dsm, acc, m0, wn, bias2, (const float*)0, 0.f, c2, h2d, b0, e0);

        group_barrier(grp);
    }
}

// ---------------------------------------------------------------------------
__global__ void init_states(const float* __restrict__ x) {
    int i0 = blockIdx.x * blockDim.x + threadIdx.x;
    int stride = gridDim.x * blockDim.x;
    unsigned* z1 = (unsigned*)g_h1;
    unsigned* z2 = (unsigned*)g_h2;
    for (int i = i0; i < HB; i += stride) { z1[i] = 0u; z2[i] = 0u; }
    for (int i = i0; i < 8 * 128; i += stride) { g_garr[i] = 0u; g_ggen[i] = 0u; }
    for (int i = i0; i < Ts * Bs; i += stride) {
        int t = i / Bs, b = i % Bs;
        g_xT[i] = x[(size_t)b * Ts + t];
    }
}

// profiling-alignment no-ops (keep ncu slot 5 on lstm_main)
__global__ void dummy_a() {}
__global__ void dummy_b() {}

__global__ void fc_kernel(const float* __restrict__ Wfc,
                          const float* __restrict__ bfc,
                          float* __restrict__ out)
{
    int b = blockIdx.x * blockDim.x + threadIdx.x;   // 0..511
    const __half* h = g_h2;   // final h2(t=511) in parity-0 buffer
    float acc = 0.f;
    #pragma unroll 8
    for (int e = 0; e < Hs; ++e)
        acc += __half2float(h[(size_t)b * Hs + e]) * Wfc[e];
    out[b] = acc + bfc[0];
}

// ---------------------------------------------------------------------------
extern "C" void kernel_launch(void* const* d_in, const int* in_sizes, int n_in,
                              void* d_out, int out_size)
{
    const float* x    = (const float*)d_in[0];
    const float* Wih0 = (const float*)d_in[1];
    const float* Whh0 = (const float*)d_in[2];
    const float* bih0 = (const float*)d_in[3];
    const float* bhh0 = (const float*)d_in[4];
    const float* Wih1 = (const float*)d_in[5];
    const float* Whh1 = (const float*)d_in[6];
    const float* bih1 = (const float*)d_in[7];
    const float* bhh1 = (const float*)d_in[8];
    const float* Wfc  = (const float*)d_in[9];
    const float* bfc  = (const float*)d_in[10];
    float* out = (float*)d_out;

    static bool attr_set = false;
    if (!attr_set) {
        cudaFuncSetAttribute(lstm_main,
            cudaFuncAttributeMaxDynamicSharedMemorySize, SMEM_BYTES);
        attr_set = true;
    }

    init_states<<<512, 256>>>(x);
    dummy_a<<<1, 32>>>();
    dummy_b<<<1, 32>>>();
    lstm_main<<<NCTA, NT, SMEM_BYTES>>>(Wih0, Whh0, bih0, bhh0,
                                        Wih1, Whh1, bih1, bhh1);
    fc_kernel<<<Bs / 256, 256>>>(Wfc, bfc, out);
}